// round 4
// baseline (speedup 1.0000x reference)
#include <cuda_runtime.h>
#include <cstdint>

#define NNZ      8000000
#define N_USERS  100000
#define N_ITEMS  50000
#define N_NODES  150000
#define D        64
#define N_HOPS   3

// ---------------- device scratch (referenced ONLY inside kernels) ----------------
__device__ int   g_cols[NNZ];                     // CSR-ordered column index
__device__ float g_w[N_HOPS][NNZ];                // CSR-ordered per-hop edge weights
__device__ int   g_counts[N_NODES];
__device__ int   g_starts[N_NODES + 1];
__device__ int   g_cursor[N_NODES];
__device__ float g_aggA[(size_t)N_NODES * D];
__device__ float g_aggB[(size_t)N_NODES * D];

// ---------------- build: zero counts ----------------
__global__ void zero_counts_kernel() {
    int i = blockIdx.x * blockDim.x + threadIdx.x;
    if (i < N_NODES) g_counts[i] = 0;
}

// ---------------- build: histogram of rows ----------------
__global__ void hist_kernel(const int* __restrict__ rows) {
    int e = blockIdx.x * blockDim.x + threadIdx.x;
    if (e < NNZ) atomicAdd(&g_counts[rows[e]], 1);
}

// ---------------- build: deterministic single-block exclusive scan ----------------
__global__ void scan_kernel() {
    const int T = 1024;
    int tid = threadIdx.x;
    const int chunk = (N_NODES + T - 1) / T;   // 147
    int begin = tid * chunk;
    int end   = begin + chunk;
    if (end > N_NODES) end = N_NODES;
    if (begin > N_NODES) begin = N_NODES;

    int sum = 0;
    for (int i = begin; i < end; ++i) sum += g_counts[i];

    __shared__ int s[T];
    s[tid] = sum;
    __syncthreads();
    // Hillis-Steele inclusive scan
    for (int off = 1; off < T; off <<= 1) {
        int v = (tid >= off) ? s[tid - off] : 0;
        __syncthreads();
        s[tid] += v;
        __syncthreads();
    }
    int run = s[tid] - sum;   // exclusive prefix for this thread's chunk
    for (int i = begin; i < end; ++i) {
        int c = g_counts[i];
        g_starts[i] = run;
        g_cursor[i] = run;
        run += c;
    }
    if (tid == T - 1) g_starts[N_NODES] = run;
}

// ---------------- build: scatter edges into CSR with pre-baked per-hop weights ----
__global__ void scatter_kernel(const int* __restrict__ rows,
                               const int* __restrict__ cols,
                               const float* __restrict__ vals,
                               const float* __restrict__ erand) {
    int e = blockIdx.x * blockDim.x + threadIdx.x;
    if (e >= NNZ) return;
    int   r = rows[e];
    float v = vals[e];
    // faithful semantics: keep = floor(0.5 + u), scale by 1/(1-0.5) = 2
    float w0 = v * floorf(0.5f + erand[e])           * 2.0f;
    float w1 = v * floorf(0.5f + erand[NNZ + e])     * 2.0f;
    float w2 = v * floorf(0.5f + erand[2 * NNZ + e]) * 2.0f;
    int pos = atomicAdd(&g_cursor[r], 1);
    g_cols[pos]  = cols[e];
    g_w[0][pos]  = w0;
    g_w[1][pos]  = w1;
    g_w[2][pos]  = w2;
}

// ---------------- init: concat embeds into aggA + write hop-0 output slice -------
__global__ void init_kernel(const float* __restrict__ ue,
                            const float* __restrict__ ie,
                            float* __restrict__ out) {
    int i = blockIdx.x * blockDim.x + threadIdx.x;      // over N_NODES*16 float4s
    if (i >= N_NODES * (D / 4)) return;
    int r = i >> 4;
    int c = i & 15;
    float4 v = (r < N_USERS) ? ((const float4*)ue)[i]
                             : ((const float4*)ie)[i - N_USERS * (D / 4)];
    ((float4*)g_aggA)[i] = v;
    // out layout: [N, 4, 64]; hop 0 slice
    ((float4*)out)[(size_t)r * (4 * D / 4) + c] = v;
}

// ---------------- hop: pull-based SpMM (warp per row) + message dropout ----------
__global__ void __launch_bounds__(256) hop_kernel(float* __restrict__ out,
                                                  const float* __restrict__ mess_rand,
                                                  int hop) {
    // ping-pong selected on DEVICE (device symbols must not cross the host boundary)
    const float* agg_in  = (hop & 1) ? g_aggB : g_aggA;
    float*       agg_out = (hop & 1) ? g_aggA : g_aggB;
    const float* wgt     = g_w[hop];

    int warp_in_blk = threadIdx.x >> 5;
    int row = blockIdx.x * (blockDim.x >> 5) + warp_in_blk;
    if (row >= N_NODES) return;
    int lane = threadIdx.x & 31;

    int s = g_starts[row];
    int e = g_starts[row + 1];

    float2 acc = make_float2(0.0f, 0.0f);

    for (int base = s; base < e; base += 32) {
        int idx = base + lane;
        int   mcol  = 0;
        float wv    = 0.0f;
        if (idx < e) {                                    // coalesced 128B + 128B per warp
            mcol = g_cols[idx];
            wv   = wgt[idx];
        }
        int wbits = __float_as_int(wv);
        int m = e - base; if (m > 32) m = 32;
        for (int j = 0; j < m; ++j) {
            float w  = __int_as_float(__shfl_sync(0xffffffffu, wbits, j));
            int  col =                 __shfl_sync(0xffffffffu, mcol,  j);
            if (w != 0.0f) {                              // warp-uniform: skip dropped edge
                float2 v = ((const float2*)(agg_in + (size_t)col * D))[lane];
                acc.x = fmaf(w, v.x, acc.x);
                acc.y = fmaf(w, v.y, acc.y);
            }
        }
    }

    // message dropout: keep if rand >= 0.1, scale 1/0.9
    const float MS = (float)(1.0 / 0.9);
    size_t off = (size_t)hop * ((size_t)N_NODES * D) + (size_t)row * D + 2 * lane;
    float2 mr = *(const float2*)(mess_rand + off);
    acc.x *= (mr.x >= 0.1f) ? MS : 0.0f;
    acc.y *= (mr.y >= 0.1f) ? MS : 0.0f;

    size_t aoff = (size_t)row * D + 2 * lane;
    *(float2*)(agg_out + aoff) = acc;
    size_t ooff = (size_t)row * (4 * D) + (size_t)(hop + 1) * D + 2 * lane;
    *(float2*)(out + ooff) = acc;
}

// ---------------- launcher ----------------
extern "C" void kernel_launch(void* const* d_in, const int* in_sizes, int n_in,
                              void* d_out, int out_size) {
    const float* user_embed = (const float*)d_in[0];
    const float* item_embed = (const float*)d_in[1];
    const int*   adj_rows   = (const int*)  d_in[2];
    const int*   adj_cols   = (const int*)  d_in[3];
    const float* adj_vals   = (const float*)d_in[4];
    const float* edge_rand  = (const float*)d_in[5];
    const float* mess_rand  = (const float*)d_in[6];
    float* out = (float*)d_out;

    // --- build CSR (edges constant across hops; per-hop weights pre-baked) ---
    zero_counts_kernel<<<(N_NODES + 255) / 256, 256>>>();
    hist_kernel<<<(NNZ + 255) / 256, 256>>>(adj_rows);
    scan_kernel<<<1, 1024>>>();
    scatter_kernel<<<(NNZ + 255) / 256, 256>>>(adj_rows, adj_cols, adj_vals, edge_rand);

    // --- hop 0 output + initial aggregation buffer ---
    init_kernel<<<(N_NODES * (D / 4) + 255) / 256, 256>>>(user_embed, item_embed, out);

    // --- 3 hops, ping-pong selected inside the kernel ---
    const int warps_per_blk = 8;
    dim3 grid((N_NODES + warps_per_blk - 1) / warps_per_blk);

    hop_kernel<<<grid, warps_per_blk * 32>>>(out, mess_rand, 0);
    hop_kernel<<<grid, warps_per_blk * 32>>>(out, mess_rand, 1);
    hop_kernel<<<grid, warps_per_blk * 32>>>(out, mess_rand, 2);
}

// round 10
// speedup vs baseline: 1.2418x; 1.2418x over previous
#include <cuda_runtime.h>
#include <cstdint>

#define NNZ      8000000
#define N_USERS  100000
#define N_ITEMS  50000
#define N_NODES  150000
#define D        64
#define N_HOPS   3

// ---------------- device scratch (referenced ONLY inside kernels) ----------------
// packed edge record: x = col | keep0<<24 | keep1<<25 | keep2<<26 ;  y = bits(val*2)
__device__ int2  g_edges[NNZ];
__device__ int   g_counts[N_NODES];
__device__ int   g_starts[N_NODES + 1];
__device__ int   g_cursor[N_NODES];
__device__ float g_aggA[(size_t)N_NODES * D];
__device__ float g_aggB[(size_t)N_NODES * D];

// ---------------- build: zero counts ----------------
__global__ void zero_counts_kernel() {
    int i = blockIdx.x * blockDim.x + threadIdx.x;
    if (i < N_NODES) g_counts[i] = 0;
}

// ---------------- build: histogram of rows ----------------
__global__ void hist_kernel(const int* __restrict__ rows) {
    int e = blockIdx.x * blockDim.x + threadIdx.x;
    if (e < NNZ) atomicAdd(&g_counts[rows[e]], 1);
}

// ---------------- build: deterministic single-block exclusive scan ----------------
__global__ void scan_kernel() {
    const int T = 1024;
    int tid = threadIdx.x;
    const int chunk = (N_NODES + T - 1) / T;   // 147
    int begin = tid * chunk;
    int end   = begin + chunk;
    if (end > N_NODES) end = N_NODES;
    if (begin > N_NODES) begin = N_NODES;

    int sum = 0;
    for (int i = begin; i < end; ++i) sum += g_counts[i];

    __shared__ int s[T];
    s[tid] = sum;
    __syncthreads();
    for (int off = 1; off < T; off <<= 1) {
        int v = (tid >= off) ? s[tid - off] : 0;
        __syncthreads();
        s[tid] += v;
        __syncthreads();
    }
    int run = s[tid] - sum;   // exclusive prefix of this thread's chunk
    for (int i = begin; i < end; ++i) {
        int c = g_counts[i];
        g_starts[i] = run;
        g_cursor[i] = run;
        run += c;
    }
    if (tid == T - 1) g_starts[N_NODES] = run;
}

// ---------------- build: scatter packed edge records (ONE 8B store / edge) ------
// keep computed with floorf — bit-faithful to reference jnp.floor(0.5 + u)
__global__ void scatter_kernel(const int* __restrict__ rows,
                               const int* __restrict__ cols,
                               const float* __restrict__ vals,
                               const float* __restrict__ erand) {
    int e = blockIdx.x * blockDim.x + threadIdx.x;
    if (e >= NNZ) return;
    int r = rows[e];
    int k0 = (int)floorf(0.5f + erand[e]);
    int k1 = (int)floorf(0.5f + erand[NNZ + e]);
    int k2 = (int)floorf(0.5f + erand[2 * NNZ + e]);
    int2 rec;
    rec.x = cols[e] | (k0 << 24) | (k1 << 25) | (k2 << 26);
    rec.y = __float_as_int(vals[e] * 2.0f);            // edge-dropout scale pre-folded
    int pos = atomicAdd(&g_cursor[r], 1);
    g_edges[pos] = rec;
}

// ---------------- init: concat embeds into aggA + write hop-0 output slice -------
// out is [N, 4, 64] -> 64 float4s per row. agg is [N, 64] -> 16 float4s per row.
__global__ void init_kernel(const float* __restrict__ ue,
                            const float* __restrict__ ie,
                            float* __restrict__ out) {
    int i = blockIdx.x * blockDim.x + threadIdx.x;      // over N_NODES*16 float4s
    if (i >= N_NODES * (D / 4)) return;
    int r = i >> 4;
    int c = i & 15;
    float4 v = (r < N_USERS) ? ((const float4*)ue)[i]
                             : ((const float4*)ie)[i - N_USERS * (D / 4)];
    ((float4*)g_aggA)[i] = v;
    ((float4*)out)[(size_t)r * 64 + c] = v;             // hop-0 slice (stride 64 float4s!)
}

// ---------------- hop: pull SpMM (warp-per-row loop, unrolled x2) ---------------
__global__ void __launch_bounds__(256) hop_kernel(float* __restrict__ out,
                                                  const float* __restrict__ mess_rand,
                                                  int hop) {
    const float* agg_in  = (hop & 1) ? g_aggB : g_aggA;
    float*       agg_out = (hop & 1) ? g_aggA : g_aggB;

    int row = blockIdx.x * (blockDim.x >> 5) + (threadIdx.x >> 5);
    if (row >= N_NODES) return;
    int lane = threadIdx.x & 31;

    int s = g_starts[row];
    int e = g_starts[row + 1];
    const int shift = 24 + hop;

    float2 acc = make_float2(0.0f, 0.0f);

    for (int base = s; base < e; base += 32) {
        int idx = base + lane;
        int2 rec = make_int2(0, 0);                    // keep bits 0 -> skipped
        if (idx < e) rec = g_edges[idx];               // coalesced 256B / warp
        int m = e - base; if (m > 32) m = 32;
        int j = 0;
        // two edges in flight per iteration (pure unroll; same lane->feature map)
        for (; j + 1 < m; j += 2) {
            int rx0 = __shfl_sync(0xffffffffu, rec.x, j);
            int ry0 = __shfl_sync(0xffffffffu, rec.y, j);
            int rx1 = __shfl_sync(0xffffffffu, rec.x, j + 1);
            int ry1 = __shfl_sync(0xffffffffu, rec.y, j + 1);
            bool k0 = (rx0 >> shift) & 1;
            bool k1 = (rx1 >> shift) & 1;
            float2 v0, v1;
            if (k0) v0 = ((const float2*)(agg_in + (size_t)(rx0 & 0x00FFFFFF) * D))[lane];
            if (k1) v1 = ((const float2*)(agg_in + (size_t)(rx1 & 0x00FFFFFF) * D))[lane];
            if (k0) {
                float w = __int_as_float(ry0);
                acc.x = fmaf(w, v0.x, acc.x);
                acc.y = fmaf(w, v0.y, acc.y);
            }
            if (k1) {
                float w = __int_as_float(ry1);
                acc.x = fmaf(w, v1.x, acc.x);
                acc.y = fmaf(w, v1.y, acc.y);
            }
        }
        if (j < m) {                                   // odd tail
            int rx0 = __shfl_sync(0xffffffffu, rec.x, j);
            int ry0 = __shfl_sync(0xffffffffu, rec.y, j);
            if ((rx0 >> shift) & 1) {
                float w = __int_as_float(ry0);
                float2 v = ((const float2*)(agg_in + (size_t)(rx0 & 0x00FFFFFF) * D))[lane];
                acc.x = fmaf(w, v.x, acc.x);
                acc.y = fmaf(w, v.y, acc.y);
            }
        }
    }

    // message dropout: keep if rand >= 0.1, scale 1/0.9
    const float MS = (float)(1.0 / 0.9);
    size_t moff = (size_t)hop * ((size_t)N_NODES * D) + (size_t)row * D + 2 * lane;
    float2 mr = *(const float2*)(mess_rand + moff);
    acc.x *= (mr.x >= 0.1f) ? MS : 0.0f;
    acc.y *= (mr.y >= 0.1f) ? MS : 0.0f;

    *(float2*)(agg_out + (size_t)row * D + 2 * lane) = acc;
    *(float2*)(out + (size_t)row * (4 * D) + (size_t)(hop + 1) * D + 2 * lane) = acc;
}

// ---------------- launcher ----------------
extern "C" void kernel_launch(void* const* d_in, const int* in_sizes, int n_in,
                              void* d_out, int out_size) {
    const float* user_embed = (const float*)d_in[0];
    const float* item_embed = (const float*)d_in[1];
    const int*   adj_rows   = (const int*)  d_in[2];
    const int*   adj_cols   = (const int*)  d_in[3];
    const float* adj_vals   = (const float*)d_in[4];
    const float* edge_rand  = (const float*)d_in[5];
    const float* mess_rand  = (const float*)d_in[6];
    float* out = (float*)d_out;

    // --- build CSR (edges constant across hops; per-hop keep bits pre-baked) ---
    zero_counts_kernel<<<(N_NODES + 255) / 256, 256>>>();
    hist_kernel<<<(NNZ + 255) / 256, 256>>>(adj_rows);
    scan_kernel<<<1, 1024>>>();
    scatter_kernel<<<(NNZ + 255) / 256, 256>>>(adj_rows, adj_cols, adj_vals, edge_rand);

    // --- hop 0 output + initial aggregation buffer ---
    init_kernel<<<(N_NODES * (D / 4) + 255) / 256, 256>>>(user_embed, item_embed, out);

    // --- 3 hops, ping-pong selected inside the kernel ---
    const int warps_per_blk = 8;
    dim3 grid((N_NODES + warps_per_blk - 1) / warps_per_blk);

    hop_kernel<<<grid, warps_per_blk * 32>>>(out, mess_rand, 0);
    hop_kernel<<<grid, warps_per_blk * 32>>>(out, mess_rand, 1);
    hop_kernel<<<grid, warps_per_blk * 32>>>(out, mess_rand, 2);
}

// round 12
// speedup vs baseline: 1.2876x; 1.0369x over previous
#include <cuda_runtime.h>
#include <cstdint>

#define NNZ      8000000
#define N_USERS  100000
#define N_ITEMS  50000
#define N_NODES  150000
#define D        64
#define N_HOPS   3

// ---------------- device scratch (referenced ONLY inside kernels) ----------------
// packed edge record: x = col | keep0<<24 | keep1<<25 | keep2<<26 ;  y = bits(val*2)
__device__ int2  g_edges[NNZ];
__device__ int   g_counts[N_NODES];
__device__ int   g_starts[N_NODES + 1];
__device__ int   g_cursor[N_NODES];
__device__ float g_aggA[(size_t)N_NODES * D];
__device__ float g_aggB[(size_t)N_NODES * D];

// ---------------- build: zero counts ----------------
__global__ void zero_counts_kernel() {
    int i = blockIdx.x * blockDim.x + threadIdx.x;
    if (i < N_NODES) g_counts[i] = 0;
}

// ---------------- build: histogram of rows (4 edges / thread, vector load) -------
__global__ void hist_kernel(const int4* __restrict__ rows4) {
    int i = blockIdx.x * blockDim.x + threadIdx.x;
    if (i >= NNZ / 4) return;
    int4 r = rows4[i];
    atomicAdd(&g_counts[r.x], 1);
    atomicAdd(&g_counts[r.y], 1);
    atomicAdd(&g_counts[r.z], 1);
    atomicAdd(&g_counts[r.w], 1);
}

// ---------------- build: deterministic single-block exclusive scan ----------------
__global__ void scan_kernel() {
    const int T = 1024;
    int tid = threadIdx.x;
    const int chunk = (N_NODES + T - 1) / T;   // 147
    int begin = tid * chunk;
    int end   = begin + chunk;
    if (end > N_NODES) end = N_NODES;
    if (begin > N_NODES) begin = N_NODES;

    int sum = 0;
    for (int i = begin; i < end; ++i) sum += g_counts[i];

    __shared__ int s[T];
    s[tid] = sum;
    __syncthreads();
    for (int off = 1; off < T; off <<= 1) {
        int v = (tid >= off) ? s[tid - off] : 0;
        __syncthreads();
        s[tid] += v;
        __syncthreads();
    }
    int run = s[tid] - sum;   // exclusive prefix of this thread's chunk
    for (int i = begin; i < end; ++i) {
        int c = g_counts[i];
        g_starts[i] = run;
        g_cursor[i] = run;
        run += c;
    }
    if (tid == T - 1) g_starts[N_NODES] = run;
}

// ---------------- build: scatter packed edge records (4 edges / thread) ----------
// keep computed with floorf — bit-faithful to reference jnp.floor(0.5 + u)
__global__ void scatter_kernel(const int4*   __restrict__ rows4,
                               const int4*   __restrict__ cols4,
                               const float4* __restrict__ vals4,
                               const float*  __restrict__ erand) {
    int i = blockIdx.x * blockDim.x + threadIdx.x;
    if (i >= NNZ / 4) return;
    int4   r = rows4[i];
    int4   c = cols4[i];
    float4 v = vals4[i];
    float4 u0 = ((const float4*)(erand))[i];                     // hop 0
    float4 u1 = ((const float4*)(erand + NNZ))[i];               // hop 1
    float4 u2 = ((const float4*)(erand + 2 * (size_t)NNZ))[i];   // hop 2

    int rr[4] = {r.x, r.y, r.z, r.w};
    int cc[4] = {c.x, c.y, c.z, c.w};
    float vv[4] = {v.x, v.y, v.z, v.w};
    float a0[4] = {u0.x, u0.y, u0.z, u0.w};
    float a1[4] = {u1.x, u1.y, u1.z, u1.w};
    float a2[4] = {u2.x, u2.y, u2.z, u2.w};

    #pragma unroll
    for (int t = 0; t < 4; ++t) {
        int k0 = (int)floorf(0.5f + a0[t]);
        int k1 = (int)floorf(0.5f + a1[t]);
        int k2 = (int)floorf(0.5f + a2[t]);
        int2 rec;
        rec.x = cc[t] | (k0 << 24) | (k1 << 25) | (k2 << 26);
        rec.y = __float_as_int(vv[t] * 2.0f);        // edge-dropout scale pre-folded
        int pos = atomicAdd(&g_cursor[rr[t]], 1);
        g_edges[pos] = rec;
    }
}

// ---------------- init: concat embeds into aggA + write hop-0 output slice -------
// out is [N, 4, 64] -> 64 float4s per row. agg is [N, 64] -> 16 float4s per row.
__global__ void init_kernel(const float* __restrict__ ue,
                            const float* __restrict__ ie,
                            float* __restrict__ out) {
    int i = blockIdx.x * blockDim.x + threadIdx.x;      // over N_NODES*16 float4s
    if (i >= N_NODES * (D / 4)) return;
    int r = i >> 4;
    int c = i & 15;
    float4 v = (r < N_USERS) ? ((const float4*)ue)[i]
                             : ((const float4*)ie)[i - N_USERS * (D / 4)];
    ((float4*)g_aggA)[i] = v;
    ((float4*)out)[(size_t)r * 64 + c] = v;             // hop-0 slice (stride 64 float4s!)
}

// ---------------- hop: pull SpMM, half-warp per edge, 4 edges in flight ----------
// Lanes 0-15 serve even edges, 16-31 odd edges; each lane covers D=64 via float4.
// Lanes past the segment hold zeroed records -> keep bit 0 -> auto-skipped, so the
// inner loop needs no bounds guards on the shfl sources (all < 32).
__global__ void __launch_bounds__(256) hop_kernel(float* __restrict__ out,
                                                  const float* __restrict__ mess_rand,
                                                  int hop) {
    const float* agg_in  = (hop & 1) ? g_aggB : g_aggA;
    float*       agg_out = (hop & 1) ? g_aggA : g_aggB;

    int row = blockIdx.x * (blockDim.x >> 5) + (threadIdx.x >> 5);
    if (row >= N_NODES) return;
    int lane = threadIdx.x & 31;
    int half = lane >> 4;          // which edge of each pair this lane serves
    int hl   = lane & 15;          // feature position: float4 index within D=64

    int s = g_starts[row];
    int e = g_starts[row + 1];
    const int shift = 24 + hop;

    float4 acc = make_float4(0.f, 0.f, 0.f, 0.f);

    for (int base = s; base < e; base += 32) {
        int idx = base + lane;
        int2 rec = make_int2(0, 0);                    // zero keep bits -> skipped
        if (idx < e) rec = g_edges[idx];               // coalesced 256B / warp
        int m = e - base; if (m > 32) m = 32;
        for (int j = 0; j < m; j += 4) {               // 4 edges per iteration
            int jj0 = j + half;                        // edges j / j+1
            int jj1 = j + 2 + half;                    // edges j+2 / j+3 (src <= 31)
            int rx0 = __shfl_sync(0xffffffffu, rec.x, jj0);
            int ry0 = __shfl_sync(0xffffffffu, rec.y, jj0);
            int rx1 = __shfl_sync(0xffffffffu, rec.x, jj1);
            int ry1 = __shfl_sync(0xffffffffu, rec.y, jj1);
            bool k0 = (rx0 >> shift) & 1;
            bool k1 = (rx1 >> shift) & 1;
            float4 v0, v1;
            if (k0) v0 = ((const float4*)(agg_in + (size_t)(rx0 & 0x00FFFFFF) * D))[hl];
            if (k1) v1 = ((const float4*)(agg_in + (size_t)(rx1 & 0x00FFFFFF) * D))[hl];
            if (k0) {
                float w = __int_as_float(ry0);
                acc.x = fmaf(w, v0.x, acc.x);
                acc.y = fmaf(w, v0.y, acc.y);
                acc.z = fmaf(w, v0.z, acc.z);
                acc.w = fmaf(w, v0.w, acc.w);
            }
            if (k1) {
                float w = __int_as_float(ry1);
                acc.x = fmaf(w, v1.x, acc.x);
                acc.y = fmaf(w, v1.y, acc.y);
                acc.z = fmaf(w, v1.z, acc.z);
                acc.w = fmaf(w, v1.w, acc.w);
            }
        }
    }

    // merge the two half-warp partial sums (same features, disjoint edge sets)
    acc.x += __shfl_xor_sync(0xffffffffu, acc.x, 16);
    acc.y += __shfl_xor_sync(0xffffffffu, acc.y, 16);
    acc.z += __shfl_xor_sync(0xffffffffu, acc.z, 16);
    acc.w += __shfl_xor_sync(0xffffffffu, acc.w, 16);

    if (half == 0) {
        const float MS = (float)(1.0 / 0.9);
        size_t moff = (size_t)hop * ((size_t)N_NODES * D) + (size_t)row * D + 4 * hl;
        float4 mr = *(const float4*)(mess_rand + moff);
        acc.x *= (mr.x >= 0.1f) ? MS : 0.0f;
        acc.y *= (mr.y >= 0.1f) ? MS : 0.0f;
        acc.z *= (mr.z >= 0.1f) ? MS : 0.0f;
        acc.w *= (mr.w >= 0.1f) ? MS : 0.0f;

        *(float4*)(agg_out + (size_t)row * D + 4 * hl) = acc;
        *(float4*)(out + (size_t)row * (4 * D) + (size_t)(hop + 1) * D + 4 * hl) = acc;
    }
}

// ---------------- launcher ----------------
extern "C" void kernel_launch(void* const* d_in, const int* in_sizes, int n_in,
                              void* d_out, int out_size) {
    const float* user_embed = (const float*)d_in[0];
    const float* item_embed = (const float*)d_in[1];
    const int*   adj_rows   = (const int*)  d_in[2];
    const int*   adj_cols   = (const int*)  d_in[3];
    const float* adj_vals   = (const float*)d_in[4];
    const float* edge_rand  = (const float*)d_in[5];
    const float* mess_rand  = (const float*)d_in[6];
    float* out = (float*)d_out;

    // --- build CSR (edges constant across hops; per-hop keep bits pre-baked) ---
    zero_counts_kernel<<<(N_NODES + 255) / 256, 256>>>();
    hist_kernel<<<(NNZ / 4 + 255) / 256, 256>>>((const int4*)adj_rows);
    scan_kernel<<<1, 1024>>>();
    scatter_kernel<<<(NNZ / 4 + 255) / 256, 256>>>((const int4*)adj_rows,
                                                   (const int4*)adj_cols,
                                                   (const float4*)adj_vals,
                                                   edge_rand);

    // --- hop 0 output + initial aggregation buffer ---
    init_kernel<<<(N_NODES * (D / 4) + 255) / 256, 256>>>(user_embed, item_embed, out);

    // --- 3 hops, ping-pong selected inside the kernel ---
    const int warps_per_blk = 8;
    dim3 grid((N_NODES + warps_per_blk - 1) / warps_per_blk);

    hop_kernel<<<grid, warps_per_blk * 32>>>(out, mess_rand, 0);
    hop_kernel<<<grid, warps_per_blk * 32>>>(out, mess_rand, 1);
    hop_kernel<<<grid, warps_per_blk * 32>>>(out, mess_rand, 2);
}

// round 14
// speedup vs baseline: 1.3130x; 1.0197x over previous
#include <cuda_runtime.h>
#include <cstdint>

#define NNZ      8000000
#define N_USERS  100000
#define N_ITEMS  50000
#define N_NODES  150000
#define D        64
#define N_HOPS   3

// ---------------- device scratch (referenced ONLY inside kernels) ----------------
// packed edge record: x = col | keep0<<24 | keep1<<25 | keep2<<26 ;  y = bits(val*2)
__device__ int2  g_edges[NNZ];
__device__ int   g_counts[N_NODES];
__device__ int   g_starts[N_NODES + 1];
__device__ int   g_cursor[N_NODES];

// ---------------- build: zero counts ----------------
__global__ void zero_counts_kernel() {
    int i = blockIdx.x * blockDim.x + threadIdx.x;
    if (i < N_NODES) g_counts[i] = 0;
}

// ---------------- build: histogram of rows (4 edges / thread, vector load) -------
__global__ void hist_kernel(const int4* __restrict__ rows4) {
    int i = blockIdx.x * blockDim.x + threadIdx.x;
    if (i >= NNZ / 4) return;
    int4 r = rows4[i];
    atomicAdd(&g_counts[r.x], 1);
    atomicAdd(&g_counts[r.y], 1);
    atomicAdd(&g_counts[r.z], 1);
    atomicAdd(&g_counts[r.w], 1);
}

// ---------------- build: deterministic single-block exclusive scan ----------------
__global__ void scan_kernel() {
    const int T = 1024;
    int tid = threadIdx.x;
    const int chunk = (N_NODES + T - 1) / T;   // 147
    int begin = tid * chunk;
    int end   = begin + chunk;
    if (end > N_NODES) end = N_NODES;
    if (begin > N_NODES) begin = N_NODES;

    int sum = 0;
    for (int i = begin; i < end; ++i) sum += g_counts[i];

    __shared__ int s[T];
    s[tid] = sum;
    __syncthreads();
    for (int off = 1; off < T; off <<= 1) {
        int v = (tid >= off) ? s[tid - off] : 0;
        __syncthreads();
        s[tid] += v;
        __syncthreads();
    }
    int run = s[tid] - sum;   // exclusive prefix of this thread's chunk
    for (int i = begin; i < end; ++i) {
        int c = g_counts[i];
        g_starts[i] = run;
        g_cursor[i] = run;
        run += c;
    }
    if (tid == T - 1) g_starts[N_NODES] = run;
}

// ---------------- build: scatter packed edge records (4 edges / thread) ----------
// keep computed with floorf — bit-faithful to reference jnp.floor(0.5 + u)
__global__ void scatter_kernel(const int4*   __restrict__ rows4,
                               const int4*   __restrict__ cols4,
                               const float4* __restrict__ vals4,
                               const float*  __restrict__ erand) {
    int i = blockIdx.x * blockDim.x + threadIdx.x;
    if (i >= NNZ / 4) return;
    int4   r = rows4[i];
    int4   c = cols4[i];
    float4 v = vals4[i];
    float4 u0 = ((const float4*)(erand))[i];                     // hop 0
    float4 u1 = ((const float4*)(erand + NNZ))[i];               // hop 1
    float4 u2 = ((const float4*)(erand + 2 * (size_t)NNZ))[i];   // hop 2

    int rr[4] = {r.x, r.y, r.z, r.w};
    int cc[4] = {c.x, c.y, c.z, c.w};
    float vv[4] = {v.x, v.y, v.z, v.w};
    float a0[4] = {u0.x, u0.y, u0.z, u0.w};
    float a1[4] = {u1.x, u1.y, u1.z, u1.w};
    float a2[4] = {u2.x, u2.y, u2.z, u2.w};

    #pragma unroll
    for (int t = 0; t < 4; ++t) {
        int k0 = (int)floorf(0.5f + a0[t]);
        int k1 = (int)floorf(0.5f + a1[t]);
        int k2 = (int)floorf(0.5f + a2[t]);
        int2 rec;
        rec.x = cc[t] | (k0 << 24) | (k1 << 25) | (k2 << 26);
        rec.y = __float_as_int(vv[t] * 2.0f);        // edge-dropout scale pre-folded
        int pos = atomicAdd(&g_cursor[rr[t]], 1);
        g_edges[pos] = rec;
    }
}

// ---------------- init: write hop-0 slice of out (out IS the agg buffer) --------
// out is [N, 4, 64] -> 64 float4s per row.
__global__ void init_kernel(const float* __restrict__ ue,
                            const float* __restrict__ ie,
                            float* __restrict__ out) {
    int i = blockIdx.x * blockDim.x + threadIdx.x;      // over N_NODES*16 float4s
    if (i >= N_NODES * (D / 4)) return;
    int r = i >> 4;
    int c = i & 15;
    float4 v = (r < N_USERS) ? ((const float4*)ue)[i]
                             : ((const float4*)ie)[i - N_USERS * (D / 4)];
    ((float4*)out)[(size_t)r * 64 + c] = v;             // hop-0 slice
}

// ---------------- hop: pull SpMM, half-warp per edge, 4 edges in flight ----------
// Reads slice `hop` of out, writes slice `hop+1`. Row stride in out = 256 floats.
// Lanes 0-15 serve even edges, 16-31 odd; each lane covers D=64 via float4.
// Lanes past the segment hold zeroed records -> keep bit 0 -> auto-skipped.
__global__ void __launch_bounds__(256) hop_kernel(float* __restrict__ out,
                                                  const float* __restrict__ mess_rand,
                                                  int hop) {
    const float* agg_in = out + (size_t)hop * D;        // row r at out + r*256 + hop*64

    int row = blockIdx.x * (blockDim.x >> 5) + (threadIdx.x >> 5);
    if (row >= N_NODES) return;
    int lane = threadIdx.x & 31;
    int half = lane >> 4;          // which edge of each pair this lane serves
    int hl   = lane & 15;          // feature position: float4 index within D=64

    int s = g_starts[row];
    int e = g_starts[row + 1];
    const int shift = 24 + hop;

    float4 acc = make_float4(0.f, 0.f, 0.f, 0.f);

    for (int base = s; base < e; base += 32) {
        int idx = base + lane;
        int2 rec = make_int2(0, 0);                    // zero keep bits -> skipped
        if (idx < e) rec = g_edges[idx];               // coalesced 256B / warp
        int m = e - base; if (m > 32) m = 32;
        for (int j = 0; j < m; j += 4) {               // 4 edges per iteration
            int jj0 = j + half;                        // edges j / j+1
            int jj1 = j + 2 + half;                    // edges j+2 / j+3 (src <= 31)
            int rx0 = __shfl_sync(0xffffffffu, rec.x, jj0);
            int ry0 = __shfl_sync(0xffffffffu, rec.y, jj0);
            int rx1 = __shfl_sync(0xffffffffu, rec.x, jj1);
            int ry1 = __shfl_sync(0xffffffffu, rec.y, jj1);
            bool k0 = (rx0 >> shift) & 1;
            bool k1 = (rx1 >> shift) & 1;
            float4 v0, v1;
            if (k0) v0 = ((const float4*)(agg_in + (size_t)(rx0 & 0x00FFFFFF) * (4 * D)))[hl];
            if (k1) v1 = ((const float4*)(agg_in + (size_t)(rx1 & 0x00FFFFFF) * (4 * D)))[hl];
            if (k0) {
                float w = __int_as_float(ry0);
                acc.x = fmaf(w, v0.x, acc.x);
                acc.y = fmaf(w, v0.y, acc.y);
                acc.z = fmaf(w, v0.z, acc.z);
                acc.w = fmaf(w, v0.w, acc.w);
            }
            if (k1) {
                float w = __int_as_float(ry1);
                acc.x = fmaf(w, v1.x, acc.x);
                acc.y = fmaf(w, v1.y, acc.y);
                acc.z = fmaf(w, v1.z, acc.z);
                acc.w = fmaf(w, v1.w, acc.w);
            }
        }
    }

    // merge the two half-warp partial sums (same features, disjoint edge sets)
    acc.x += __shfl_xor_sync(0xffffffffu, acc.x, 16);
    acc.y += __shfl_xor_sync(0xffffffffu, acc.y, 16);
    acc.z += __shfl_xor_sync(0xffffffffu, acc.z, 16);
    acc.w += __shfl_xor_sync(0xffffffffu, acc.w, 16);

    if (half == 0) {
        const float MS = (float)(1.0 / 0.9);
        size_t moff = (size_t)hop * ((size_t)N_NODES * D) + (size_t)row * D + 4 * hl;
        float4 mr = *(const float4*)(mess_rand + moff);
        acc.x *= (mr.x >= 0.1f) ? MS : 0.0f;
        acc.y *= (mr.y >= 0.1f) ? MS : 0.0f;
        acc.z *= (mr.z >= 0.1f) ? MS : 0.0f;
        acc.w *= (mr.w >= 0.1f) ? MS : 0.0f;

        // write slice hop+1 (next hop's input AND final output)
        *(float4*)(out + (size_t)row * (4 * D) + (size_t)(hop + 1) * D + 4 * hl) = acc;
    }
}

// ---------------- launcher ----------------
extern "C" void kernel_launch(void* const* d_in, const int* in_sizes, int n_in,
                              void* d_out, int out_size) {
    const float* user_embed = (const float*)d_in[0];
    const float* item_embed = (const float*)d_in[1];
    const int*   adj_rows   = (const int*)  d_in[2];
    const int*   adj_cols   = (const int*)  d_in[3];
    const float* adj_vals   = (const float*)d_in[4];
    const float* edge_rand  = (const float*)d_in[5];
    const float* mess_rand  = (const float*)d_in[6];
    float* out = (float*)d_out;

    // --- build CSR (edges constant across hops; per-hop keep bits pre-baked) ---
    zero_counts_kernel<<<(N_NODES + 255) / 256, 256>>>();
    hist_kernel<<<(NNZ / 4 + 255) / 256, 256>>>((const int4*)adj_rows);
    scan_kernel<<<1, 1024>>>();
    scatter_kernel<<<(NNZ / 4 + 255) / 256, 256>>>((const int4*)adj_rows,
                                                   (const int4*)adj_cols,
                                                   (const float4*)adj_vals,
                                                   edge_rand);

    // --- hop 0 output slice (out doubles as the aggregation buffer) ---
    init_kernel<<<(N_NODES * (D / 4) + 255) / 256, 256>>>(user_embed, item_embed, out);

    // --- 3 hops, in-place through out's hop slices ---
    const int warps_per_blk = 8;
    dim3 grid((N_NODES + warps_per_blk - 1) / warps_per_blk);

    hop_kernel<<<grid, warps_per_blk * 32>>>(out, mess_rand, 0);
    hop_kernel<<<grid, warps_per_blk * 32>>>(out, mess_rand, 1);
    hop_kernel<<<grid, warps_per_blk * 32>>>(out, mess_rand, 2);
}